// round 7
// baseline (speedup 1.0000x reference)
#include <cuda_runtime.h>
#include <cstdint>

#define BB       2048
#define INF      512
#define OUTF     512
#define NEXP     64
#define T        256
#define MTMAX    64          // max rows per chunk (8 warps x r<=8)
#define NT       128         // out cols per block
#define KT       16          // k per tile
#define NTILES   (INF / KT)  // 32
#define WROW     20          // 16 k-floats + 4 pad (stride 80B -> conflict-free LDS.128)
#define XROW     16
#define NSTAGE   3

__device__ __forceinline__ void ffma2(unsigned long long &d,
                                      unsigned long long a,
                                      unsigned long long b) {
    asm("fma.rn.f32x2 %0, %1, %2, %0;" : "+l"(d) : "l"(a), "l"(b));
}

__device__ __forceinline__ void cp16(uint32_t dst, const void* src) {
    asm volatile("cp.async.ca.shared.global [%0], [%1], 16;\n"
                 :: "r"(dst), "l"(src));
}

union F2U { unsigned long long u; float f[2]; };

__global__ __launch_bounds__(T, 2)
void catlin_kernel(const float* __restrict__ x,
                   const unsigned* __restrict__ idw,
                   const float* __restrict__ weight,
                   float* __restrict__ out)
{
    __shared__ float Ws[NSTAGE][NT * WROW];     // 3*10240B
    __shared__ float Xs[NSTAGE][MTMAX * XROW];  // 3*4096B
    __shared__ uint16_t slist[BB];              // 4096B
    __shared__ int scount;
    __shared__ unsigned sor;

    const int expert = blockIdx.x >> 2;
    const int otile  = blockIdx.x & 3;
    const int tid    = threadIdx.x;

    if (tid == 0) { scount = 0; sor = 0; }
    __syncthreads();

    // int64 vs int32 id detection (touch only first 2048 words: in-bounds either way)
    unsigned myor = 0;
    for (int i = tid; i < BB / 2; i += T) myor |= idw[2 * i + 1];
    if (myor) atomicOr(&sor, myor);
    __syncthreads();
    const bool is64 = (sor == 0);

    for (int i = tid; i < BB; i += T) {
        int id = is64 ? (int)idw[2 * i] : (int)idw[i];
        if (id == expert) {
            int p = atomicAdd(&scount, 1);
            slist[p] = (uint16_t)i;
        }
    }
    __syncthreads();
    const int m = scount;
    if (m == 0) return;

    // Even distribution: every warp owns r rows -> all warps active for any m.
    const int r     = (m + 7) >> 3;                  // rows per warp (<=8 when m<=64)
    const int chunk = (r < 8 ? r : 8) * 8;           // rows per outer chunk (<=64)
    const int rw    = (r < 8 ? r : 8);               // rows per warp per chunk

    const float* wbase = weight + ((size_t)expert * OUTF + (size_t)otile * NT) * INF;

    const int mg = tid >> 5;   // warp id 0..7 -> rows [mg*rw, (mg+1)*rw) within chunk
    const int ng = tid & 31;   // lane -> out cols {ng, ng+32, ng+64, ng+96}
    const int m0 = mg * rw;

    uint32_t wsm[NSTAGE], xsm[NSTAGE];
    #pragma unroll
    for (int b = 0; b < NSTAGE; b++) {
        wsm[b] = (uint32_t)__cvta_generic_to_shared(&Ws[b][0]);
        xsm[b] = (uint32_t)__cvta_generic_to_shared(&Xs[b][0]);
    }

    // X tile copy: up to 256 float4 per tile, 1 per thread
    const int x_mr = tid >> 2;
    const int x_k4 = tid & 3;

    for (int mb = 0; mb < m; mb += chunk) {
        unsigned long long acc[8][4];
        #pragma unroll
        for (int i = 0; i < 8; i++)
            #pragma unroll
            for (int j = 0; j < 4; j++) acc[i][j] = 0ULL;

        const bool xcopy = (x_mr < chunk);
        int xrow = mb + x_mr; if (xrow >= m) xrow = m - 1;   // pad: duplicate last
        const float* xsrc_row = x + (size_t)slist[xrow] * INF + x_k4 * 4;

        auto issue_tile = [&](int t) {
            const int buf = t % NSTAGE;
            const int kb  = t * KT;
            // W tile: 512 float4, 2 per thread (fully coalesced: idx = 2*tid+it)
            #pragma unroll
            for (int it = 0; it < 2; ++it) {
                int idx = 2 * tid + it;
                int o   = idx >> 2;
                int k4  = idx & 3;
                cp16(wsm[buf] + (uint32_t)(o * WROW + k4 * 4) * 4,
                     wbase + (size_t)o * INF + kb + k4 * 4);
            }
            if (xcopy)
                cp16(xsm[buf] + (uint32_t)(x_mr * XROW + x_k4 * 4) * 4,
                     xsrc_row + kb);
            asm volatile("cp.async.commit_group;\n" ::);
        };

        issue_tile(0);
        issue_tile(1);

        for (int t = 0; t < NTILES; ++t) {
            if (t + 1 < NTILES) {
                asm volatile("cp.async.wait_group 1;\n" ::);
            } else {
                asm volatile("cp.async.wait_group 0;\n" ::);
            }
            __syncthreads();

            {
                const int buf = t % NSTAGE;
                const float* Wb = &Ws[buf][0];
                const float* Xb = &Xs[buf][0];
                #pragma unroll
                for (int kq = 0; kq < KT / 4; ++kq) {
                    // Batch all loads for this k-quad, then a pure FFMA2 burst.
                    ulonglong2 wv[4];
                    #pragma unroll
                    for (int j = 0; j < 4; ++j)
                        wv[j] = *(const ulonglong2*)(Wb + (ng + 32 * j) * WROW + kq * 4);
                    ulonglong2 xvv[8];
                    #pragma unroll
                    for (int i = 0; i < 8; ++i)
                        if (i < rw)   // uniform per block
                            xvv[i] = *(const ulonglong2*)(Xb + (m0 + i) * XROW + kq * 4);
                    #pragma unroll
                    for (int i = 0; i < 8; ++i) {
                        if (i < rw) {
                            #pragma unroll
                            for (int j = 0; j < 4; ++j) {
                                ffma2(acc[i][j], xvv[i].x, wv[j].x);
                                ffma2(acc[i][j], xvv[i].y, wv[j].y);
                            }
                        }
                    }
                }
            }

            if (t + 2 < NTILES) issue_tile(t + 2);
        }

        // epilogue: per-row stores; lanes 0..31 cover 128 consecutive bytes per j
        #pragma unroll
        for (int i = 0; i < 8; ++i) {
            if (i < rw) {
                int row = mb + m0 + i;
                if (row < m) {
                    float* obase = out + (size_t)slist[row] * OUTF + otile * NT;
                    #pragma unroll
                    for (int j = 0; j < 4; ++j) {
                        F2U u; u.u = acc[i][j];
                        obase[ng + 32 * j] = u.f[0] + u.f[1];
                    }
                }
            }
        }
        __syncthreads();   // protect smem stages before next chunk
    }
}

extern "C" void kernel_launch(void* const* d_in, const int* in_sizes, int n_in,
                              void* d_out, int out_size)
{
    const float*    x   = nullptr;
    const unsigned* ids = nullptr;
    const float*    w   = nullptr;
    for (int i = 0; i < n_in; ++i) {
        if (in_sizes[i] == BB)                     ids = (const unsigned*)d_in[i];
        else if (in_sizes[i] == BB * INF)          x   = (const float*)d_in[i];
        else if (in_sizes[i] == NEXP * OUTF * INF) w   = (const float*)d_in[i];
    }
    catlin_kernel<<<NEXP * 4, T>>>(x, ids, w, (float*)d_out);
}

// round 15
// speedup vs baseline: 2.1143x; 2.1143x over previous
#include <cuda_runtime.h>
#include <cstdint>

#define BB     2048
#define INF    512
#define OUTF   512
#define NEXP   64
#define T      256
#define MCH    48            // m rows per chunk: 3 x m16 tiles
#define KT     32            // fp32 k per tile -> 2 k16 mma steps
#define NTILES (INF / KT)    // 16

#define SWZ(o)  ((o) ^ (((o) >> 3) & 0x70))
#define WBUF(s) ((uint32_t)(s) * 32768u)            // 256 rows x 128B (hi|lo)
#define ABUF(s) (65536u + (uint32_t)(s) * 6144u)    // 48 rows x 128B (hi|lo)
#define DYN_BYTES (65536 + 12288 + 1024)

static __device__ __forceinline__ void sts32(uint32_t a, uint32_t v) {
    asm volatile("st.shared.b32 [%0], %1;" :: "r"(a), "r"(v));
}
// split fp32 pair -> bf16x2 hi (truncate) + bf16x2 lo (rn of residual); elem0 = .x
static __device__ __forceinline__ void cvt_pair(float2 v, uint32_t &hi2, uint32_t &lo2) {
    uint32_t a = __float_as_uint(v.x), b = __float_as_uint(v.y);
    hi2 = __byte_perm(a, b, 0x7632);
    float la = v.x - __uint_as_float(a & 0xFFFF0000u);
    float lb = v.y - __uint_as_float(b & 0xFFFF0000u);
    asm("cvt.rn.bf16x2.f32 %0, %1, %2;" : "=r"(lo2) : "f"(lb), "f"(la));
}
#define LDSM4(r0,r1,r2,r3,a) asm volatile( \
    "ldmatrix.sync.aligned.m8n8.x4.shared.b16 {%0,%1,%2,%3}, [%4];" \
    : "=r"(r0),"=r"(r1),"=r"(r2),"=r"(r3) : "r"(a))
#define LDSM2(r0,r1,a) asm volatile( \
    "ldmatrix.sync.aligned.m8n8.x2.shared.b16 {%0,%1}, [%2];" \
    : "=r"(r0),"=r"(r1) : "r"(a))
#define MMA(c,a,b) asm volatile( \
    "mma.sync.aligned.m16n8k16.row.col.f32.bf16.bf16.f32 " \
    "{%0,%1,%2,%3}, {%4,%5,%6,%7}, {%8,%9}, {%0,%1,%2,%3};" \
    : "+f"((c)[0]),"+f"((c)[1]),"+f"((c)[2]),"+f"((c)[3]) \
    : "r"((a)[0]),"r"((a)[1]),"r"((a)[2]),"r"((a)[3]),"r"((b)[0]),"r"((b)[1]))

extern __shared__ char dynsmem[];

__global__ __launch_bounds__(T)
void catlin_mma(const float* __restrict__ x, const unsigned* __restrict__ idw,
                const float* __restrict__ weight, float* __restrict__ out)
{
    __shared__ uint16_t slist[BB];
    __shared__ int scount;
    __shared__ unsigned sor;

    const int expert = blockIdx.x >> 1;
    const int nhh    = blockIdx.x & 1;
    const int tid    = threadIdx.x;
    const int wid    = tid >> 5, lane = tid & 31;

    if (tid == 0) { scount = 0; sor = 0; }
    __syncthreads();

    // int64 vs int32 id detection (first 2048 words are in-bounds either way)
    unsigned myor = 0;
    for (int i = tid; i < BB / 2; i += T) myor |= idw[2 * i + 1];
    if (myor) atomicOr(&sor, myor);
    __syncthreads();
    const bool is64 = (sor == 0);

    for (int i = tid; i < BB; i += T) {
        int id = is64 ? (int)idw[2 * i] : (int)idw[i];
        if (id == expert) { int p = atomicAdd(&scount, 1); slist[p] = (uint16_t)i; }
    }
    __syncthreads();
    const int m = scount;
    if (m == 0) return;

    uint32_t sb = (uint32_t)__cvta_generic_to_shared(dynsmem);
    sb = (sb + 1023u) & ~1023u;

    const float* wexp = weight + ((size_t)(expert * OUTF + nhh * 256)) * INF;
    const int n0w = wid * 32;        // this warp's 32 output columns
    const int r8  = lane & 7;        // ldmatrix address role
    const int g4  = lane >> 3;

    float2 wst[16], ast[3];          // staged fp32 for next tile

    for (int mbase = 0; mbase < m; mbase += MCH) {
        const int rem = m - mbase;
        const int nmt = rem >= 33 ? 3 : (rem >= 17 ? 2 : 1);

        float c[3][4][4];
        #pragma unroll
        for (int a = 0; a < 3; a++)
            #pragma unroll
            for (int b = 0; b < 4; b++)
                #pragma unroll
                for (int q = 0; q < 4; q++) c[a][b][q] = 0.f;

        auto ldg = [&](int t) {
            const int kb = t * KT;
            #pragma unroll
            for (int i = 0; i < 16; ++i) {           // W: 256 rows x 16 float2
                int idx = i * T + tid;
                int row = idx >> 4, c2 = idx & 15;
                wst[i] = *(const float2*)(wexp + (size_t)row * INF + kb + c2 * 2);
            }
            #pragma unroll
            for (int i = 0; i < 3; ++i) {            // A: 48 rows x 16 float2
                int idx = i * T + tid;
                int row = idx >> 4, c2 = idx & 15;
                int gr = mbase + row; if (gr >= m) gr = m - 1;
                ast[i] = *(const float2*)(x + (size_t)slist[gr] * INF + kb + c2 * 2);
            }
        };
        auto sts = [&](int s) {
            #pragma unroll
            for (int i = 0; i < 16; ++i) {
                int idx = i * T + tid;
                int row = idx >> 4, c2 = idx & 15;
                uint32_t h, l; cvt_pair(wst[i], h, l);
                sts32(sb + WBUF(s) + SWZ((uint32_t)(row * 128 + c2 * 4)), h);
                sts32(sb + WBUF(s) + SWZ((uint32_t)(row * 128 + 64 + c2 * 4)), l);
            }
            #pragma unroll
            for (int i = 0; i < 3; ++i) {
                int idx = i * T + tid;
                int row = idx >> 4, c2 = idx & 15;
                uint32_t h, l; cvt_pair(ast[i], h, l);
                sts32(sb + ABUF(s) + SWZ((uint32_t)(row * 128 + c2 * 4)), h);
                sts32(sb + ABUF(s) + SWZ((uint32_t)(row * 128 + 64 + c2 * 4)), l);
            }
        };

        ldg(0);
        sts(0);
        __syncthreads();

        for (int t = 0; t < NTILES; ++t) {
            if (t + 1 < NTILES) ldg(t + 1);
            const int s = t & 1;

            #pragma unroll
            for (int kk = 0; kk < 2; ++kk) {         // two k16 steps per tile
                uint32_t bh[4][2], bl[4][2];
                const uint32_t kb0 = kk * 32 + (g4 & 1) * 16;
                #pragma unroll
                for (int nt = 0; nt < 4; ++nt) {
                    uint32_t rowb = (uint32_t)(n0w + nt * 8 + r8);
                    LDSM2(bh[nt][0], bh[nt][1], sb + WBUF(s) + SWZ(rowb * 128 + kb0));
                    LDSM2(bl[nt][0], bl[nt][1], sb + WBUF(s) + SWZ(rowb * 128 + kb0 + 64));
                }
                const uint32_t ka0 = kk * 32 + (g4 >> 1) * 16;
                #pragma unroll
                for (int mt = 0; mt < 3; ++mt) {
                    if (mt < nmt) {                  // uniform per block
                        uint32_t rowa = (uint32_t)(mt * 16 + r8 + (g4 & 1) * 8);
                        uint32_t ah[4], al[4];
                        LDSM4(ah[0], ah[1], ah[2], ah[3],
                              sb + ABUF(s) + SWZ(rowa * 128 + ka0));
                        LDSM4(al[0], al[1], al[2], al[3],
                              sb + ABUF(s) + SWZ(rowa * 128 + ka0 + 64));
                        #pragma unroll
                        for (int nt = 0; nt < 4; ++nt) {
                            MMA(c[mt][nt], ah, bh[nt]);
                            MMA(c[mt][nt], ah, bl[nt]);
                            MMA(c[mt][nt], al, bh[nt]);
                        }
                    }
                }
            }

            if (t + 1 < NTILES) sts((t + 1) & 1);
            __syncthreads();
        }

        // epilogue: d frag -> out. c0,c1: row=lane/4, cols 2(lane%4)+{0,1}; c2,c3: row+8
        const int gcol = (lane & 3) * 2;
        const int grow = lane >> 2;
        #pragma unroll
        for (int mt = 0; mt < 3; ++mt) {
            if (mt < nmt) {
                #pragma unroll
                for (int h = 0; h < 2; ++h) {
                    int lr = mt * 16 + grow + h * 8;
                    int gr = mbase + lr;
                    if (gr < m) {
                        float* ob = out + (size_t)slist[gr] * OUTF + nhh * 256 + n0w;
                        #pragma unroll
                        for (int nt = 0; nt < 4; ++nt) {
                            float2 v = make_float2(c[mt][nt][2 * h], c[mt][nt][2 * h + 1]);
                            *(float2*)(ob + nt * 8 + gcol) = v;
                        }
                    }
                }
            }
        }
        __syncthreads();   // protect smem buffers before next chunk's prologue
    }
}

extern "C" void kernel_launch(void* const* d_in, const int* in_sizes, int n_in,
                              void* d_out, int out_size)
{
    const float*    x   = nullptr;
    const unsigned* ids = nullptr;
    const float*    w   = nullptr;
    for (int i = 0; i < n_in; ++i) {
        if (in_sizes[i] == BB)                     ids = (const unsigned*)d_in[i];
        else if (in_sizes[i] == BB * INF)          x   = (const float*)d_in[i];
        else if (in_sizes[i] == NEXP * OUTF * INF) w   = (const float*)d_in[i];
    }
    cudaFuncSetAttribute(catlin_mma, cudaFuncAttributeMaxDynamicSharedMemorySize, DYN_BYTES);
    catlin_mma<<<NEXP * 2, T, DYN_BYTES>>>(x, ids, w, (float*)d_out);
}